// round 1
// baseline (speedup 1.0000x reference)
#include <cuda_runtime.h>
#include <cstdint>

#define BATCH   8192
#define IN_DIM  256
#define HID_DIM 16384
#define OUT_DIM 256
#define K_SEL   256
#define LIST_CAP 512

// Scratch: dec_w transposed to [HID_DIM][OUT_DIM] so a hidden unit's output
// weights are contiguous (1 KB, coalesced) during the sparse decode GEMM.
__device__ float g_dec_wT[(size_t)HID_DIM * OUT_DIM];

// ---------------------------------------------------------------------------
// Kernel 1: transpose dec_w [OUT_DIM][HID_DIM] -> g_dec_wT [HID_DIM][OUT_DIM]
// ---------------------------------------------------------------------------
__global__ void transpose_dec(const float* __restrict__ dec_w)
{
    __shared__ float tile[32][33];
    const int j0 = blockIdx.x * 32;   // hid index
    const int o0 = blockIdx.y * 32;   // out index
    const int tx = threadIdx.x;       // 0..31
    const int ty = threadIdx.y;       // 0..7
#pragma unroll
    for (int i = 0; i < 4; i++) {
        tile[ty + i * 8][tx] = dec_w[(size_t)(o0 + ty + i * 8) * HID_DIM + (j0 + tx)];
    }
    __syncthreads();
#pragma unroll
    for (int i = 0; i < 4; i++) {
        g_dec_wT[(size_t)(j0 + ty + i * 8) * OUT_DIM + (o0 + tx)] = tile[tx][ty + i * 8];
    }
}

// ---------------------------------------------------------------------------
// Kernel 2: h_relu = relu(x @ enc_w^T + enc_b)   [BATCH][HID_DIM]
// fp32 SIMT tiled GEMM. BM=BN=128, BK=16, 256 threads, 8x8 per thread,
// double-buffered SMEM (32 KB static).
// ---------------------------------------------------------------------------
__global__ __launch_bounds__(256, 2)
void gemm1_relu(const float* __restrict__ x,
                const float* __restrict__ w,
                const float* __restrict__ bias,
                float* __restrict__ h)
{
    __shared__ float As[2][16][128];   // [k][m]
    __shared__ float Bs[2][16][128];   // [k][n]

    const int tid = threadIdx.x;
    const int m0 = blockIdx.y * 128;
    const int n0 = blockIdx.x * 128;

    const int ty = tid >> 4;          // 0..15 (row group)
    const int tx = tid & 15;          // 0..15 (col group)

    float acc[8][8];
#pragma unroll
    for (int i = 0; i < 8; i++)
#pragma unroll
        for (int j = 0; j < 8; j++) acc[i][j] = 0.0f;

    // Load mapping: 512 float4 per operand per stage, 2 per thread.
    // f = tid + 256*i ; row = f>>2 ; kq = f&3
    const int r0 = (tid + 0)   >> 2, kq0 = (tid + 0)   & 3;
    const int r1 = (tid + 256) >> 2, kq1 = (tid + 256) & 3;

    float4 xa0, xa1, wa0, wa1;

    // prologue: stage 0
    {
        const int k0 = 0;
        xa0 = *(const float4*)&x[(size_t)(m0 + r0) * IN_DIM + k0 + kq0 * 4];
        xa1 = *(const float4*)&x[(size_t)(m0 + r1) * IN_DIM + k0 + kq1 * 4];
        wa0 = *(const float4*)&w[(size_t)(n0 + r0) * IN_DIM + k0 + kq0 * 4];
        wa1 = *(const float4*)&w[(size_t)(n0 + r1) * IN_DIM + k0 + kq1 * 4];
        As[0][kq0 * 4 + 0][r0] = xa0.x; As[0][kq0 * 4 + 1][r0] = xa0.y;
        As[0][kq0 * 4 + 2][r0] = xa0.z; As[0][kq0 * 4 + 3][r0] = xa0.w;
        As[0][kq1 * 4 + 0][r1] = xa1.x; As[0][kq1 * 4 + 1][r1] = xa1.y;
        As[0][kq1 * 4 + 2][r1] = xa1.z; As[0][kq1 * 4 + 3][r1] = xa1.w;
        Bs[0][kq0 * 4 + 0][r0] = wa0.x; Bs[0][kq0 * 4 + 1][r0] = wa0.y;
        Bs[0][kq0 * 4 + 2][r0] = wa0.z; Bs[0][kq0 * 4 + 3][r0] = wa0.w;
        Bs[0][kq1 * 4 + 0][r1] = wa1.x; Bs[0][kq1 * 4 + 1][r1] = wa1.y;
        Bs[0][kq1 * 4 + 2][r1] = wa1.z; Bs[0][kq1 * 4 + 3][r1] = wa1.w;
    }
    __syncthreads();

    const int NSTAGE = IN_DIM / 16;   // 16
    for (int s = 0; s < NSTAGE; s++) {
        const int cur = s & 1;
        const int nxt = cur ^ 1;
        if (s + 1 < NSTAGE) {
            const int k0 = (s + 1) * 16;
            xa0 = *(const float4*)&x[(size_t)(m0 + r0) * IN_DIM + k0 + kq0 * 4];
            xa1 = *(const float4*)&x[(size_t)(m0 + r1) * IN_DIM + k0 + kq1 * 4];
            wa0 = *(const float4*)&w[(size_t)(n0 + r0) * IN_DIM + k0 + kq0 * 4];
            wa1 = *(const float4*)&w[(size_t)(n0 + r1) * IN_DIM + k0 + kq1 * 4];
        }

#pragma unroll
        for (int kk = 0; kk < 16; kk++) {
            float a[8], b[8];
            *(float4*)&a[0] = *(const float4*)&As[cur][kk][ty * 8 + 0];
            *(float4*)&a[4] = *(const float4*)&As[cur][kk][ty * 8 + 4];
            *(float4*)&b[0] = *(const float4*)&Bs[cur][kk][tx * 8 + 0];
            *(float4*)&b[4] = *(const float4*)&Bs[cur][kk][tx * 8 + 4];
#pragma unroll
            for (int i = 0; i < 8; i++)
#pragma unroll
                for (int j = 0; j < 8; j++)
                    acc[i][j] = fmaf(a[i], b[j], acc[i][j]);
        }

        if (s + 1 < NSTAGE) {
            As[nxt][kq0 * 4 + 0][r0] = xa0.x; As[nxt][kq0 * 4 + 1][r0] = xa0.y;
            As[nxt][kq0 * 4 + 2][r0] = xa0.z; As[nxt][kq0 * 4 + 3][r0] = xa0.w;
            As[nxt][kq1 * 4 + 0][r1] = xa1.x; As[nxt][kq1 * 4 + 1][r1] = xa1.y;
            As[nxt][kq1 * 4 + 2][r1] = xa1.z; As[nxt][kq1 * 4 + 3][r1] = xa1.w;
            Bs[nxt][kq0 * 4 + 0][r0] = wa0.x; Bs[nxt][kq0 * 4 + 1][r0] = wa0.y;
            Bs[nxt][kq0 * 4 + 2][r0] = wa0.z; Bs[nxt][kq0 * 4 + 3][r0] = wa0.w;
            Bs[nxt][kq1 * 4 + 0][r1] = wa1.x; Bs[nxt][kq1 * 4 + 1][r1] = wa1.y;
            Bs[nxt][kq1 * 4 + 2][r1] = wa1.z; Bs[nxt][kq1 * 4 + 3][r1] = wa1.w;
        }
        __syncthreads();
    }

    // epilogue: bias + relu, write h
    float bv[8];
    *(float4*)&bv[0] = *(const float4*)&bias[n0 + tx * 8 + 0];
    *(float4*)&bv[4] = *(const float4*)&bias[n0 + tx * 8 + 4];

#pragma unroll
    for (int i = 0; i < 8; i++) {
        const size_t grow = (size_t)(m0 + ty * 8 + i) * HID_DIM + n0 + tx * 8;
        float4 v0, v1;
        float t;
        t = acc[i][0] + bv[0]; v0.x = t > 0.0f ? t : 0.0f;
        t = acc[i][1] + bv[1]; v0.y = t > 0.0f ? t : 0.0f;
        t = acc[i][2] + bv[2]; v0.z = t > 0.0f ? t : 0.0f;
        t = acc[i][3] + bv[3]; v0.w = t > 0.0f ? t : 0.0f;
        t = acc[i][4] + bv[4]; v1.x = t > 0.0f ? t : 0.0f;
        t = acc[i][5] + bv[5]; v1.y = t > 0.0f ? t : 0.0f;
        t = acc[i][6] + bv[6]; v1.z = t > 0.0f ? t : 0.0f;
        t = acc[i][7] + bv[7]; v1.w = t > 0.0f ? t : 0.0f;
        *(float4*)&h[grow + 0] = v0;
        *(float4*)&h[grow + 4] = v1;
    }
}

// ---------------------------------------------------------------------------
// Kernel 3: per-row exact top-K threshold (32-bit radix select), apply
// threshold (write hidden_post), sparse decode GEMM (+dec_b) -> output row.
// One CTA (256 threads) per batch row. Row staged in dynamic SMEM (64 KB).
// ---------------------------------------------------------------------------
__global__ void topk_apply_gemm2(const float* __restrict__ dec_b,
                                 float* __restrict__ out,      // [BATCH][OUT_DIM]
                                 float* __restrict__ hidden)   // [BATCH][HID_DIM]
{
    extern __shared__ float row[];            // HID_DIM floats
    __shared__ unsigned hist[256];
    __shared__ unsigned s_prefix;
    __shared__ int s_r;
    __shared__ int scan[256];
    __shared__ int list_j[LIST_CAP];
    __shared__ float list_v[LIST_CAP];
    __shared__ int s_total;

    const int tid = threadIdx.x;
    const int brow = blockIdx.x;
    float* hrow = hidden + (size_t)brow * HID_DIM;

    // stage row into smem (coalesced float4)
    {
        const float4* src = (const float4*)hrow;
        float4* dst = (float4*)row;
        for (int i = tid; i < HID_DIM / 4; i += 256) dst[i] = src[i];
    }
    if (tid == 0) { s_prefix = 0u; s_r = K_SEL; }
    __syncthreads();

    // ---- 4-pass radix select (MSB first) for K-th largest exact key ----
    for (int shift = 24; shift >= 0; shift -= 8) {
        hist[tid] = 0u;
        __syncthreads();
        const unsigned prefix = s_prefix;
        const unsigned himask = (shift == 24) ? 0u : (0xFFFFFFFFu << (shift + 8));
        for (int i = tid; i < HID_DIM; i += 256) {
            const unsigned u = __float_as_uint(row[i]);
            const bool cand = ((u & himask) == (prefix & himask));
            const unsigned d = (u >> shift) & 255u;
            const unsigned active = __ballot_sync(0xffffffffu, cand);
            if (cand) {
                // warp-aggregated histogram update (pass 1 digits are highly
                // concentrated in a few exponent bins)
                const unsigned peers = __match_any_sync(active, d);
                const int leader = __ffs(peers) - 1;
                if ((int)(threadIdx.x & 31) == leader)
                    atomicAdd(&hist[d], (unsigned)__popc(peers));
            }
        }
        __syncthreads();
        if (tid == 0) {
            int r = s_r;
            unsigned acc = 0;
            int d = 255;
            for (; d > 0; --d) {
                const unsigned c = hist[d];
                if (acc + c >= (unsigned)r) break;
                acc += c;
            }
            s_prefix = prefix | ((unsigned)d << shift);
            s_r = r - (int)acc;
        }
        __syncthreads();
    }
    const float t = __uint_as_float(s_prefix);
    const bool dense_path = !(t > 0.0f);   // threshold 0 keeps everything

    // ---- deterministic compaction of kept (j, v) pairs ----
    int cnt = 0;
    if (!dense_path) {
        for (int i = tid; i < HID_DIM; i += 256)
            if (row[i] >= t) cnt++;
    }
    scan[tid] = cnt;
    __syncthreads();
#pragma unroll
    for (int off = 1; off < 256; off <<= 1) {
        const int add = (tid >= off) ? scan[tid - off] : 0;
        __syncthreads();
        scan[tid] += add;
        __syncthreads();
    }
    if (tid == 255) s_total = scan[255];
    int base = scan[tid] - cnt;
    __syncthreads();

    if (!dense_path) {
        for (int i = tid; i < HID_DIM; i += 256) {
            const float v = row[i];
            if (v >= t) {
                if (base < LIST_CAP) { list_j[base] = i; list_v[base] = v; }
                base++;
            } else {
                row[i] = 0.0f;
            }
        }
    }
    __syncthreads();

    // ---- write hidden_post back (row now holds post-threshold values) ----
    {
        const float4* src = (const float4*)row;
        float4* dst = (float4*)hrow;
        for (int i = tid; i < HID_DIM / 4; i += 256) dst[i] = src[i];
    }

    // ---- sparse decode GEMM: out[brow][tid] = dec_b[tid] + sum v * dec_wT[j][tid]
    float acc = dec_b[tid];
    if (!dense_path) {
        const int nsel = (s_total < LIST_CAP) ? s_total : LIST_CAP;
        int s = 0;
        for (; s + 4 <= nsel; s += 4) {
            acc = fmaf(list_v[s + 0], g_dec_wT[(size_t)list_j[s + 0] * OUT_DIM + tid], acc);
            acc = fmaf(list_v[s + 1], g_dec_wT[(size_t)list_j[s + 1] * OUT_DIM + tid], acc);
            acc = fmaf(list_v[s + 2], g_dec_wT[(size_t)list_j[s + 2] * OUT_DIM + tid], acc);
            acc = fmaf(list_v[s + 3], g_dec_wT[(size_t)list_j[s + 3] * OUT_DIM + tid], acc);
        }
        for (; s < nsel; s++)
            acc = fmaf(list_v[s], g_dec_wT[(size_t)list_j[s] * OUT_DIM + tid], acc);
    } else {
        for (int j = 0; j < HID_DIM; j++)
            acc = fmaf(row[j], g_dec_wT[(size_t)j * OUT_DIM + tid], acc);
    }
    out[(size_t)brow * OUT_DIM + tid] = acc;
}

// ---------------------------------------------------------------------------
// Launch
// ---------------------------------------------------------------------------
extern "C" void kernel_launch(void* const* d_in, const int* in_sizes, int n_in,
                              void* d_out, int out_size)
{
    const float* x     = (const float*)d_in[0];   // [BATCH][IN_DIM]
    const float* enc_w = (const float*)d_in[1];   // [HID_DIM][IN_DIM]
    const float* enc_b = (const float*)d_in[2];   // [HID_DIM]
    const float* dec_w = (const float*)d_in[3];   // [OUT_DIM][HID_DIM]
    const float* dec_b = (const float*)d_in[4];   // [OUT_DIM]
    // d_in[5] = k (always 256 for this problem)

    float* out    = (float*)d_out;                          // [BATCH][OUT_DIM]
    float* hidden = (float*)d_out + (size_t)BATCH * OUT_DIM; // [BATCH][HID_DIM]

    static int attr_done = 0;
    // (idempotent; cheap to repeat — no static-guard semantics affecting work)
    cudaFuncSetAttribute(topk_apply_gemm2,
                         cudaFuncAttributeMaxDynamicSharedMemorySize,
                         HID_DIM * sizeof(float));
    (void)attr_done;

    // 1) transpose dec_w
    {
        dim3 grid(HID_DIM / 32, OUT_DIM / 32);
        dim3 block(32, 8);
        transpose_dec<<<grid, block>>>(dec_w);
    }
    // 2) encoder GEMM + relu -> hidden region of d_out
    {
        dim3 grid(HID_DIM / 128, BATCH / 128);
        gemm1_relu<<<grid, 256>>>(x, enc_w, enc_b, hidden);
    }
    // 3) per-row top-k threshold + apply + sparse decode
    {
        topk_apply_gemm2<<<BATCH, 256, HID_DIM * sizeof(float)>>>(dec_b, out, hidden);
    }
}